// round 1
// baseline (speedup 1.0000x reference)
#include <cuda_runtime.h>
#include <cuda_bf16.h>
#include <math.h>

// Problem constants
#define BB 32
#define NN 1000
#define CC 64
#define HF 12
#define WF 20
#define DD 768          // C*HF
#define NM1 999         // N-1
#define YD 72
#define OUTC 77         // 2 + 2 + 73

// ---------------------------------------------------------------------------
// Scratch (device globals; no runtime allocation allowed)
// ---------------------------------------------------------------------------
__device__ float g_feat[BB * NN * DD];        // (B,N,768)
__device__ float g_logits[BB * NN * NM1];     // (B,N,999)
__device__ float g_S[BB * NN * NN];           // (B,N,N) scattered softmax, zero diag
__device__ float g_att[BB * NN * DD];         // (B,N,768)
__device__ int   g_mask_mode;                 // 1 = byte mask, 0 = 4-byte mask

// ---------------------------------------------------------------------------
// Mask dtype detection: if every aligned 32-bit word of the mask buffer is in
// {0, 1, 0x3F800000} it is a 4-byte dtype (int32 or float32 -> nonzero test
// identical); otherwise it is packed bytes (bool/uint8).
// Scans 190000 words = 760000 bytes, safe for both layouts (768000 elements).
// ---------------------------------------------------------------------------
__global__ void detect_mask_kernel(const unsigned int* __restrict__ w, int nwords)
{
    __shared__ int bad;
    if (threadIdx.x == 0) bad = 0;
    __syncthreads();
    int local = 0;
    for (int k = threadIdx.x; k < nwords; k += blockDim.x) {
        unsigned int v = w[k];
        if (v != 0u && v != 1u && v != 0x3F800000u) local = 1;
    }
    if (local) bad = 1;
    __syncthreads();
    if (threadIdx.x == 0) g_mask_mode = bad;   // 1 => byte mask
}

// ---------------------------------------------------------------------------
// Gather: feat[b,n,d] = invalid ? 0 : fv[b, z[n,d], y[n,d], x[n,d]]
// ---------------------------------------------------------------------------
__global__ void gather_kernel(const float* __restrict__ fv,
                              const int* __restrict__ z,
                              const int* __restrict__ y,
                              const int* __restrict__ x,
                              const void* __restrict__ mask,
                              float* __restrict__ feat,
                              int total)
{
    int idx = blockIdx.x * blockDim.x + threadIdx.x;
    if (idx >= total) return;
    int d = idx % DD;
    int rest = idx / DD;
    int n = rest % NN;
    int b = rest / NN;
    int nd = n * DD + d;

    bool inv;
    if (g_mask_mode)
        inv = ((const unsigned char*)mask)[nd] != 0;
    else
        inv = ((const unsigned int*)mask)[nd] != 0u;

    float v = 0.f;
    if (!inv) {
        int zz = z[nd], yy = y[nd], xx = x[nd];
        v = fv[((b * CC + zz) * HF + yy) * WF + xx];
    }
    feat[idx] = v;
}

// ---------------------------------------------------------------------------
// Generic fp32 tiled GEMM: C[b] = A[b] (MxK, row-major) @ B[b] (KxN, row-major)
// BM=BN=64, BK=16, 256 threads, 4x4 per-thread micro-tile.
// ---------------------------------------------------------------------------
template<bool ADD_BIAS>
__global__ void gemm64_kernel(const float* __restrict__ A,
                              const float* __restrict__ B,
                              const float* __restrict__ bias,
                              float* __restrict__ C,
                              int M, int N, int K,
                              size_t sA, size_t sB, size_t sC)
{
    __shared__ float As[16][65];   // As[k][m], padded
    __shared__ float Bs[16][64];   // Bs[k][n]

    const int tid = threadIdx.x;
    const int tx = tid & 15, ty = tid >> 4;
    const int m0 = blockIdx.y * 64, n0 = blockIdx.x * 64;

    A += (size_t)blockIdx.z * sA;
    B += (size_t)blockIdx.z * sB;
    C += (size_t)blockIdx.z * sC;

    float acc[4][4];
    #pragma unroll
    for (int i = 0; i < 4; i++)
        #pragma unroll
        for (int j = 0; j < 4; j++) acc[i][j] = 0.f;

    const int aRow = tid >> 2;         // 0..63
    const int aCol = (tid & 3) * 4;    // 0,4,8,12
    const int bRow = tid >> 4;         // 0..15
    const int bCol = (tid & 15) * 4;   // 0..60

    for (int kt = 0; kt < K; kt += 16) {
        #pragma unroll
        for (int i = 0; i < 4; i++) {
            int k = kt + aCol + i;
            int m = m0 + aRow;
            As[aCol + i][aRow] = (m < M && k < K) ? A[(size_t)m * K + k] : 0.f;
        }
        #pragma unroll
        for (int i = 0; i < 4; i++) {
            int k = kt + bRow;
            int n = n0 + bCol + i;
            Bs[bRow][bCol + i] = (k < K && n < N) ? B[(size_t)k * N + n] : 0.f;
        }
        __syncthreads();
        #pragma unroll
        for (int kk = 0; kk < 16; kk++) {
            float a[4], bb[4];
            #pragma unroll
            for (int i = 0; i < 4; i++) a[i] = As[kk][ty + 16 * i];
            #pragma unroll
            for (int j = 0; j < 4; j++) bb[j] = Bs[kk][tx + 16 * j];
            #pragma unroll
            for (int i = 0; i < 4; i++)
                #pragma unroll
                for (int j = 0; j < 4; j++)
                    acc[i][j] += a[i] * bb[j];
        }
        __syncthreads();
    }

    #pragma unroll
    for (int i = 0; i < 4; i++) {
        int m = m0 + ty + 16 * i;
        if (m >= M) continue;
        #pragma unroll
        for (int j = 0; j < 4; j++) {
            int n = n0 + tx + 16 * j;
            if (n < N) {
                float v = acc[i][j];
                if (ADD_BIAS) v += bias[n];
                C[(size_t)m * N + n] = v;
            }
        }
    }
}

// ---------------------------------------------------------------------------
// Row softmax over 999 logits + scatter into (N x N) with zero diagonal.
// One block per (row i, batch b).
// ---------------------------------------------------------------------------
__global__ void softmax_scatter_kernel(const float* __restrict__ logits,
                                       float* __restrict__ S)
{
    const int i = blockIdx.x;
    const int b = blockIdx.y;
    const float* __restrict__ row = logits + ((size_t)(b * NN + i)) * NM1;
    float* __restrict__ o = S + ((size_t)(b * NN + i)) * NN;

    __shared__ float sh[8];
    const int tid = threadIdx.x;
    const int lane = tid & 31, warp = tid >> 5;

    // cache this thread's elements (<= 4)
    float rv[4];
    #pragma unroll
    for (int p = 0; p < 4; p++) {
        int k = tid + 256 * p;
        rv[p] = (k < NM1) ? row[k] : -1e30f;
    }

    // max
    float m = -1e30f;
    #pragma unroll
    for (int p = 0; p < 4; p++) m = fmaxf(m, rv[p]);
    #pragma unroll
    for (int off = 16; off; off >>= 1) m = fmaxf(m, __shfl_xor_sync(0xffffffffu, m, off));
    if (lane == 0) sh[warp] = m;
    __syncthreads();
    if (warp == 0) {
        float t = (lane < 8) ? sh[lane] : -1e30f;
        #pragma unroll
        for (int off = 16; off; off >>= 1) t = fmaxf(t, __shfl_xor_sync(0xffffffffu, t, off));
        if (lane == 0) sh[0] = t;
    }
    __syncthreads();
    m = sh[0];
    __syncthreads();

    // sum of exp
    float s = 0.f;
    float ev[4];
    #pragma unroll
    for (int p = 0; p < 4; p++) {
        int k = tid + 256 * p;
        float e = (k < NM1) ? __expf(rv[p] - m) : 0.f;
        ev[p] = e;
        s += e;
    }
    #pragma unroll
    for (int off = 16; off; off >>= 1) s += __shfl_xor_sync(0xffffffffu, s, off);
    if (lane == 0) sh[warp] = s;
    __syncthreads();
    if (warp == 0) {
        float t = (lane < 8) ? sh[lane] : 0.f;
        #pragma unroll
        for (int off = 16; off; off >>= 1) t += __shfl_xor_sync(0xffffffffu, t, off);
        if (lane == 0) sh[0] = t;
    }
    __syncthreads();
    const float inv = 1.f / sh[0];

    // scatter with diagonal skip
    #pragma unroll
    for (int p = 0; p < 4; p++) {
        int k = tid + 256 * p;
        if (k < NM1) {
            int j = (k < i) ? k : k + 1;
            o[j] = ev[p] * inv;
        }
    }
    if (tid == 0) o[i] = 0.f;
}

// ---------------------------------------------------------------------------
// Heads: for each flat row r (b*1000+n), cat = [att_r (768), feat_r (768)];
// 75 dot products of length 1536 (2 cls + 73 reg), fused with bias+anchor add.
// Block = 32 rows x all 75 cols. 1000 blocks.
// ---------------------------------------------------------------------------
__global__ void heads_kernel(const float* __restrict__ att,
                             const float* __restrict__ feat,
                             const float* __restrict__ cls_w,
                             const float* __restrict__ cls_b,
                             const float* __restrict__ reg_w,
                             const float* __restrict__ reg_b,
                             const float* __restrict__ anchors,
                             float* __restrict__ out)
{
    __shared__ float catS[32][65];
    __shared__ float wS[64][76];

    const int tid = threadIdx.x;
    const int r0 = blockIdx.x * 32;
    const int rowl = tid >> 3;   // 0..31
    const int cg = tid & 7;      // 0..7

    float acc[10];
    #pragma unroll
    for (int j = 0; j < 10; j++) acc[j] = 0.f;

    for (int kc = 0; kc < 2 * DD; kc += 64) {
        // stage 32x64 chunk of cat
        for (int t = tid; t < 32 * 64; t += 256) {
            int rr = t >> 6, kk = t & 63;
            int k = kc + kk;
            size_t r = (size_t)(r0 + rr);
            float v = (k < DD) ? att[r * DD + k] : feat[r * DD + (k - DD)];
            catS[rr][kk] = v;
        }
        // stage 64x75 weights
        for (int t = tid; t < 64 * 75; t += 256) {
            int kk = t / 75, c = t % 75;
            int k = kc + kk;
            float w = (c < 2) ? cls_w[k * 2 + c] : reg_w[k * 73 + (c - 2)];
            wS[kk][c] = w;
        }
        __syncthreads();
        #pragma unroll 4
        for (int kk = 0; kk < 64; kk++) {
            float a = catS[rowl][kk];
            #pragma unroll
            for (int j = 0; j < 10; j++) {
                int c = cg + 8 * j;
                if (c < 75) acc[j] += a * wS[kk][c];
            }
        }
        __syncthreads();
    }

    const int r = r0 + rowl;
    const int n = r % NN;
    #pragma unroll
    for (int j = 0; j < 10; j++) {
        int c = cg + 8 * j;
        if (c < 75) {
            float v; int oc;
            if (c < 2) { v = acc[j] + cls_b[c]; oc = c; }
            else {
                int t2 = c - 2;
                v = acc[j] + reg_b[t2] + anchors[n * OUTC + 4 + t2];
                oc = c + 2;
            }
            out[(size_t)r * OUTC + oc] = v;
        }
    }
    if (tid < 32) {
        int rr = r0 + tid;
        int nn = rr % NN;
        out[(size_t)rr * OUTC + 2] = anchors[nn * OUTC + 2];
        out[(size_t)rr * OUTC + 3] = anchors[nn * OUTC + 3];
    }
}

// ---------------------------------------------------------------------------
// Launch
// ---------------------------------------------------------------------------
extern "C" void kernel_launch(void* const* d_in, const int* in_sizes, int n_in,
                              void* d_out, int out_size)
{
    const float* fv      = (const float*)d_in[0];
    const float* attn_w  = (const float*)d_in[1];
    const float* attn_b  = (const float*)d_in[2];
    const float* cls_w   = (const float*)d_in[3];
    const float* cls_b   = (const float*)d_in[4];
    const float* reg_w   = (const float*)d_in[5];
    const float* reg_b   = (const float*)d_in[6];
    const float* anchors = (const float*)d_in[7];
    const int*   z       = (const int*)d_in[8];
    const int*   y       = (const int*)d_in[9];
    const int*   x       = (const int*)d_in[10];
    const void*  mask    = d_in[11];
    float* out = (float*)d_out;

    float *feat, *logits, *S, *att;
    cudaGetSymbolAddress((void**)&feat,   g_feat);
    cudaGetSymbolAddress((void**)&logits, g_logits);
    cudaGetSymbolAddress((void**)&S,      g_S);
    cudaGetSymbolAddress((void**)&att,    g_att);

    // 1) mask dtype detection (safe word count for byte or 4-byte layout)
    detect_mask_kernel<<<1, 256>>>((const unsigned int*)mask, 190000);

    // 2) gather
    {
        int total = BB * NN * DD;
        gather_kernel<<<(total + 255) / 256, 256>>>(fv, z, y, x, mask, feat, total);
    }

    // 3) logits = feat @ attn_w + attn_b     (per batch: 1000x999, K=768)
    {
        dim3 grid((NM1 + 63) / 64, (NN + 63) / 64, BB);
        gemm64_kernel<true><<<grid, 256>>>(feat, attn_w, attn_b, logits,
                                           NN, NM1, DD,
                                           (size_t)NN * DD, 0, (size_t)NN * NM1);
    }

    // 4) softmax rows + scatter to full NxN with zero diagonal
    {
        dim3 grid(NN, BB);
        softmax_scatter_kernel<<<grid, 256>>>(logits, S);
    }

    // 5) att = S @ feat                      (per batch: 1000x768, K=1000)
    {
        dim3 grid((DD + 63) / 64, (NN + 63) / 64, BB);
        gemm64_kernel<false><<<grid, 256>>>(S, feat, nullptr, att,
                                            NN, DD, NN,
                                            (size_t)NN * NN, (size_t)NN * DD,
                                            (size_t)NN * DD);
    }

    // 6) heads + anchor/bias epilogue
    heads_kernel<<<(BB * NN) / 32, 256>>>(att, feat, cls_w, cls_b,
                                          reg_w, reg_b, anchors, out);
}

// round 6
// speedup vs baseline: 1.5859x; 1.5859x over previous
#include <cuda_runtime.h>
#include <cuda_bf16.h>
#include <math.h>

// Problem constants
#define BB 32
#define NN 1000
#define CC 64
#define HF 12
#define WF 20
#define DD 768          // C*HF
#define NM1 999         // N-1
#define YD 72
#define OUTC 77         // 2 + 2 + 73
#define HN 75           // heads output cols (2 cls + 73 reg)

// ---------------------------------------------------------------------------
// Scratch (device globals; no runtime allocation allowed)
// ---------------------------------------------------------------------------
__device__ float g_feat[BB * NN * DD];        // (B,N,768)
__device__ float g_logits[BB * NN * NM1];     // (B,N,999)
__device__ float g_S[BB * NN * NN];           // (B,N,N) scattered softmax, zero diag
__device__ float g_att[BB * NN * DD];         // (B,N,768)
__device__ float g_ho[BB * NN * HN];          // heads GEMM result (32000 x 75)
__device__ float g_W[2 * DD * HN];            // packed [cls_w | reg_w] (1536 x 75)
__device__ int   g_mask_mode;                 // 1 = byte mask, 0 = 4-byte mask

// ---------------------------------------------------------------------------
// Mask dtype detection (bool/uint8 vs int32/float32)
// ---------------------------------------------------------------------------
__global__ __launch_bounds__(256)
void detect_mask_kernel(const unsigned int* __restrict__ w, int nwords)
{
    __shared__ int bad;
    if (threadIdx.x == 0) bad = 0;
    __syncthreads();
    int local = 0;
    for (int k = threadIdx.x; k < nwords; k += blockDim.x) {
        unsigned int v = w[k];
        if (v != 0u && v != 1u && v != 0x3F800000u) local = 1;
    }
    if (local) bad = 1;
    __syncthreads();
    if (threadIdx.x == 0) g_mask_mode = bad;   // 1 => byte mask
}

// ---------------------------------------------------------------------------
// Gather: feat[b,n,d] = invalid ? 0 : fv[b, z[n,d], y[n,d], x[n,d]]
// ---------------------------------------------------------------------------
__global__ __launch_bounds__(256)
void gather_kernel(const float* __restrict__ fv,
                   const int* __restrict__ z,
                   const int* __restrict__ y,
                   const int* __restrict__ x,
                   const void* __restrict__ mask,
                   float* __restrict__ feat,
                   int total)
{
    int idx = blockIdx.x * blockDim.x + threadIdx.x;
    if (idx >= total) return;
    int d = idx % DD;
    int rest = idx / DD;
    int n = rest % NN;
    int b = rest / NN;
    int nd = n * DD + d;

    bool inv;
    if (g_mask_mode)
        inv = ((const unsigned char*)mask)[nd] != 0;
    else
        inv = ((const unsigned int*)mask)[nd] != 0u;

    float v = 0.f;
    if (!inv) {
        int zz = z[nd], yy = y[nd], xx = x[nd];
        v = fv[((b * CC + zz) * HF + yy) * WF + xx];
    }
    feat[idx] = v;
}

// ---------------------------------------------------------------------------
// Pack heads weights: g_W[k][c] = c<2 ? cls_w[k][c] : reg_w[k][c-2]
// ---------------------------------------------------------------------------
__global__ __launch_bounds__(256)
void pack_w_kernel(const float* __restrict__ cls_w,
                   const float* __restrict__ reg_w,
                   float* __restrict__ W)
{
    int idx = blockIdx.x * blockDim.x + threadIdx.x;
    if (idx >= 2 * DD * HN) return;
    int k = idx / HN, c = idx % HN;
    W[idx] = (c < 2) ? cls_w[k * 2 + c] : reg_w[k * 73 + (c - 2)];
}

// ---------------------------------------------------------------------------
// TF32 tensor-core GEMM: C[z] = A[z] (MxK row-major) @ B[z] (KxN row-major)
// Block tile 128x128, K tile 32. 8 warps (4 rows x 2 cols), warp tile 32x64.
// mma.sync.m16n8k8.tf32 with fp32 accumulate.
// MODE 0: plain A (stride lda). MODE 1: concat A = [A1 | A2], each row-major
//         M x DD (k<DD reads A1, else A2).
// ---------------------------------------------------------------------------
__device__ __forceinline__ unsigned int f2tf32(float f)
{
    unsigned int r;
    asm("cvt.rna.tf32.f32 %0, %1;" : "=r"(r) : "f"(f));
    return r;
}

template<int MODE, bool ADD_BIAS>
__global__ __launch_bounds__(256)
void gemm_tf32_kernel(const float* __restrict__ A,
                      const float* __restrict__ A2,
                      const float* __restrict__ B,
                      const float* __restrict__ bias,
                      float* __restrict__ C,
                      int M, int N, int K, int lda, int ldb,
                      size_t sA, size_t sB, size_t sC)
{
    __shared__ float As[32][129];   // [k][m], tf32-rounded
    __shared__ float Bs[32][129];   // [k][n], tf32-rounded

    const int tid  = threadIdx.x;
    const int lane = tid & 31;
    const int wid  = tid >> 5;
    const int gid  = lane >> 2;     // 0..7
    const int tg   = lane & 3;      // 0..3
    const int wm   = (wid & 3) * 32;
    const int wn   = (wid >> 2) * 64;

    const int m0 = blockIdx.y * 128;
    const int n0 = blockIdx.x * 128;

    if (MODE == 0) {
        A += (size_t)blockIdx.z * sA;
    }
    B += (size_t)blockIdx.z * sB;
    C += (size_t)blockIdx.z * sC;

    float c[2][8][4];
    #pragma unroll
    for (int i = 0; i < 2; i++)
        #pragma unroll
        for (int j = 0; j < 8; j++)
            #pragma unroll
            for (int q = 0; q < 4; q++) c[i][j][q] = 0.f;

    for (int kt = 0; kt < K; kt += 32) {
        // --- load A tile: 128 rows x 32 k, coalesced over k ---
        #pragma unroll
        for (int p = 0; p < 16; p++) {
            int idx = tid + p * 256;
            int m_l = idx >> 5, k_l = idx & 31;
            int m = m0 + m_l, kg = kt + k_l;
            float v = 0.f;
            if (m < M && kg < K) {
                if (MODE == 1)
                    v = (kg < DD) ? A[(size_t)m * DD + kg]
                                  : A2[(size_t)m * DD + (kg - DD)];
                else
                    v = A[(size_t)m * lda + kg];
            }
            As[k_l][m_l] = __uint_as_float(f2tf32(v));
        }
        // --- load B tile: 32 k x 128 n, coalesced over n ---
        #pragma unroll
        for (int p = 0; p < 16; p++) {
            int idx = tid + p * 256;
            int k_l = idx >> 7, n_l = idx & 127;
            int kg = kt + k_l, n = n0 + n_l;
            float v = (kg < K && n < N) ? B[(size_t)kg * ldb + n] : 0.f;
            Bs[k_l][n_l] = __uint_as_float(f2tf32(v));
        }
        __syncthreads();

        #pragma unroll
        for (int ks = 0; ks < 4; ks++) {
            const int k0 = ks * 8;
            unsigned int a[2][4], bf[8][2];
            #pragma unroll
            for (int mt = 0; mt < 2; mt++) {
                int ar = wm + mt * 16 + gid;
                a[mt][0] = __float_as_uint(As[k0 + tg][ar]);
                a[mt][1] = __float_as_uint(As[k0 + tg][ar + 8]);
                a[mt][2] = __float_as_uint(As[k0 + tg + 4][ar]);
                a[mt][3] = __float_as_uint(As[k0 + tg + 4][ar + 8]);
            }
            #pragma unroll
            for (int nt = 0; nt < 8; nt++) {
                int bc = wn + nt * 8 + gid;
                bf[nt][0] = __float_as_uint(Bs[k0 + tg][bc]);
                bf[nt][1] = __float_as_uint(Bs[k0 + tg + 4][bc]);
            }
            #pragma unroll
            for (int mt = 0; mt < 2; mt++)
                #pragma unroll
                for (int nt = 0; nt < 8; nt++) {
                    asm volatile(
                        "mma.sync.aligned.m16n8k8.row.col.f32.tf32.tf32.f32 "
                        "{%0,%1,%2,%3}, {%4,%5,%6,%7}, {%8,%9}, {%0,%1,%2,%3};\n"
                        : "+f"(c[mt][nt][0]), "+f"(c[mt][nt][1]),
                          "+f"(c[mt][nt][2]), "+f"(c[mt][nt][3])
                        : "r"(a[mt][0]), "r"(a[mt][1]), "r"(a[mt][2]), "r"(a[mt][3]),
                          "r"(bf[nt][0]), "r"(bf[nt][1]));
                }
        }
        __syncthreads();
    }

    // --- epilogue ---
    #pragma unroll
    for (int mt = 0; mt < 2; mt++) {
        #pragma unroll
        for (int nt = 0; nt < 8; nt++) {
            int row0 = m0 + wm + mt * 16 + gid;
            int col0 = n0 + wn + nt * 8 + tg * 2;
            #pragma unroll
            for (int q = 0; q < 4; q++) {
                int row = row0 + (q >> 1) * 8;
                int col = col0 + (q & 1);
                if (row < M && col < N) {
                    float v = c[mt][nt][q];
                    if (ADD_BIAS) v += bias[col];
                    C[(size_t)row * N + col] = v;
                }
            }
        }
    }
}

// ---------------------------------------------------------------------------
// Row softmax over 999 logits + scatter into (N x N) with zero diagonal.
// ---------------------------------------------------------------------------
__global__ __launch_bounds__(256)
void softmax_scatter_kernel(const float* __restrict__ logits,
                            float* __restrict__ S)
{
    const int i = blockIdx.x;
    const int b = blockIdx.y;
    const float* __restrict__ row = logits + ((size_t)(b * NN + i)) * NM1;
    float* __restrict__ o = S + ((size_t)(b * NN + i)) * NN;

    __shared__ float sh[8];
    const int tid = threadIdx.x;
    const int lane = tid & 31, warp = tid >> 5;

    float rv[4];
    #pragma unroll
    for (int p = 0; p < 4; p++) {
        int k = tid + 256 * p;
        rv[p] = (k < NM1) ? row[k] : -1e30f;
    }

    float m = -1e30f;
    #pragma unroll
    for (int p = 0; p < 4; p++) m = fmaxf(m, rv[p]);
    #pragma unroll
    for (int off = 16; off; off >>= 1) m = fmaxf(m, __shfl_xor_sync(0xffffffffu, m, off));
    if (lane == 0) sh[warp] = m;
    __syncthreads();
    if (warp == 0) {
        float t = (lane < 8) ? sh[lane] : -1e30f;
        #pragma unroll
        for (int off = 16; off; off >>= 1) t = fmaxf(t, __shfl_xor_sync(0xffffffffu, t, off));
        if (lane == 0) sh[0] = t;
    }
    __syncthreads();
    m = sh[0];
    __syncthreads();

    float s = 0.f;
    float ev[4];
    #pragma unroll
    for (int p = 0; p < 4; p++) {
        int k = tid + 256 * p;
        float e = (k < NM1) ? __expf(rv[p] - m) : 0.f;
        ev[p] = e;
        s += e;
    }
    #pragma unroll
    for (int off = 16; off; off >>= 1) s += __shfl_xor_sync(0xffffffffu, s, off);
    if (lane == 0) sh[warp] = s;
    __syncthreads();
    if (warp == 0) {
        float t = (lane < 8) ? sh[lane] : 0.f;
        #pragma unroll
        for (int off = 16; off; off >>= 1) t += __shfl_xor_sync(0xffffffffu, t, off);
        if (lane == 0) sh[0] = t;
    }
    __syncthreads();
    const float inv = 1.f / sh[0];

    #pragma unroll
    for (int p = 0; p < 4; p++) {
        int k = tid + 256 * p;
        if (k < NM1) {
            int j = (k < i) ? k : k + 1;
            o[j] = ev[p] * inv;
        }
    }
    if (tid == 0) o[i] = 0.f;
}

// ---------------------------------------------------------------------------
// Heads epilogue: out[r][c] from ho (32000 x 75), biases, anchors.
// ---------------------------------------------------------------------------
__global__ __launch_bounds__(256)
void heads_epilogue_kernel(const float* __restrict__ ho,
                           const float* __restrict__ cls_b,
                           const float* __restrict__ reg_b,
                           const float* __restrict__ anchors,
                           float* __restrict__ out)
{
    int idx = blockIdx.x * blockDim.x + threadIdx.x;
    if (idx >= BB * NN * OUTC) return;
    int c = idx % OUTC;
    int r = idx / OUTC;
    int n = r % NN;
    float v;
    if (c < 2)       v = ho[(size_t)r * HN + c] + cls_b[c];
    else if (c < 4)  v = anchors[n * OUTC + c];
    else             v = ho[(size_t)r * HN + (c - 2)] + reg_b[c - 4]
                         + anchors[n * OUTC + c];
    out[idx] = v;
}

// ---------------------------------------------------------------------------
// Launch
// ---------------------------------------------------------------------------
extern "C" void kernel_launch(void* const* d_in, const int* in_sizes, int n_in,
                              void* d_out, int out_size)
{
    const float* fv      = (const float*)d_in[0];
    const float* attn_w  = (const float*)d_in[1];
    const float* attn_b  = (const float*)d_in[2];
    const float* cls_w   = (const float*)d_in[3];
    const float* cls_b   = (const float*)d_in[4];
    const float* reg_w   = (const float*)d_in[5];
    const float* reg_b   = (const float*)d_in[6];
    const float* anchors = (const float*)d_in[7];
    const int*   z       = (const int*)d_in[8];
    const int*   y       = (const int*)d_in[9];
    const int*   x       = (const int*)d_in[10];
    const void*  mask    = d_in[11];
    float* out = (float*)d_out;

    float *feat, *logits, *S, *att, *ho, *W;
    cudaGetSymbolAddress((void**)&feat,   g_feat);
    cudaGetSymbolAddress((void**)&logits, g_logits);
    cudaGetSymbolAddress((void**)&S,      g_S);
    cudaGetSymbolAddress((void**)&att,    g_att);
    cudaGetSymbolAddress((void**)&ho,     g_ho);
    cudaGetSymbolAddress((void**)&W,      g_W);

    // 1) mask dtype detection
    detect_mask_kernel<<<1, 256>>>((const unsigned int*)mask, 190000);

    // 2) gather
    {
        int total = BB * NN * DD;
        gather_kernel<<<(total + 255) / 256, 256>>>(fv, z, y, x, mask, feat, total);
    }

    // 2b) pack heads weights
    pack_w_kernel<<<(2 * DD * HN + 255) / 256, 256>>>(cls_w, reg_w, W);

    // 3) logits = feat @ attn_w + attn_b   (per batch 1000x999, K=768)
    {
        dim3 grid((NM1 + 127) / 128, (NN + 127) / 128, BB);
        gemm_tf32_kernel<0, true><<<grid, 256>>>(
            feat, nullptr, attn_w, attn_b, logits,
            NN, NM1, DD, DD, NM1,
            (size_t)NN * DD, 0, (size_t)NN * NM1);
    }

    // 4) softmax + scatter
    {
        dim3 grid(NN, BB);
        softmax_scatter_kernel<<<grid, 256>>>(logits, S);
    }

    // 5) att = S @ feat                    (per batch 1000x768, K=1000)
    {
        dim3 grid((DD + 127) / 128, (NN + 127) / 128, BB);
        gemm_tf32_kernel<0, false><<<grid, 256>>>(
            S, nullptr, feat, nullptr, att,
            NN, DD, NN, NN, DD,
            (size_t)NN * NN, (size_t)NN * DD, (size_t)NN * DD);
    }

    // 6) heads GEMM: [att|feat] (32000 x 1536) @ W (1536 x 75)
    {
        dim3 grid(1, (BB * NN + 127) / 128, 1);
        gemm_tf32_kernel<1, false><<<grid, 256>>>(
            att, feat, W, nullptr, ho,
            BB * NN, HN, 2 * DD, 0, HN,
            0, 0, 0);
    }

    // 7) heads epilogue
    {
        int total = BB * NN * OUTC;
        heads_epilogue_kernel<<<(total + 255) / 256, 256>>>(ho, cls_b, reg_b,
                                                            anchors, out);
    }
}

// round 7
// speedup vs baseline: 1.6496x; 1.0402x over previous
#include <cuda_runtime.h>
#include <cuda_bf16.h>
#include <math.h>

// Problem constants
#define BB 32
#define NN 1000
#define CC 64
#define HF 12
#define WF 20
#define DD 768          // C*HF
#define NM1 999         // N-1
#define YD 72
#define OUTC 77         // 2 + 2 + 73
#define HN 75           // heads output cols (2 cls + 73 reg)

// ---------------------------------------------------------------------------
// Scratch (device globals; no runtime allocation allowed)
// ---------------------------------------------------------------------------
__device__ float g_feat[BB * NN * DD];        // (B,N,768)
__device__ float g_logits[BB * NN * NM1];     // (B,N,999)
__device__ float g_S[BB * NN * NN];           // (B,N,N) scattered softmax, zero diag
__device__ float g_att[BB * NN * DD];         // (B,N,768)
__device__ float g_ho[BB * NN * HN];          // heads GEMM result (32000 x 75)
__device__ float g_W[2 * DD * HN];            // packed [cls_w | reg_w] (1536 x 75)
__device__ int   g_mask_mode;                 // 1 = byte mask, 0 = 4-byte mask

// ---------------------------------------------------------------------------
// Mask dtype detection (bool/uint8 vs int32/float32)
// ---------------------------------------------------------------------------
__global__ __launch_bounds__(256)
void detect_mask_kernel(const unsigned int* __restrict__ w, int nwords)
{
    __shared__ int bad;
    if (threadIdx.x == 0) bad = 0;
    __syncthreads();
    int local = 0;
    for (int k = threadIdx.x; k < nwords; k += blockDim.x) {
        unsigned int v = w[k];
        if (v != 0u && v != 1u && v != 0x3F800000u) local = 1;
    }
    if (local) bad = 1;
    __syncthreads();
    if (threadIdx.x == 0) g_mask_mode = bad;   // 1 => byte mask
}

// ---------------------------------------------------------------------------
// Gather: feat[b,n,d] = invalid ? 0 : fv[b, z[n,d], y[n,d], x[n,d]]
// ---------------------------------------------------------------------------
__global__ __launch_bounds__(256)
void gather_kernel(const float* __restrict__ fv,
                   const int* __restrict__ z,
                   const int* __restrict__ y,
                   const int* __restrict__ x,
                   const void* __restrict__ mask,
                   float* __restrict__ feat,
                   int total)
{
    int idx = blockIdx.x * blockDim.x + threadIdx.x;
    if (idx >= total) return;
    int d = idx % DD;
    int rest = idx / DD;
    int n = rest % NN;
    int b = rest / NN;
    int nd = n * DD + d;

    bool inv;
    if (g_mask_mode)
        inv = ((const unsigned char*)mask)[nd] != 0;
    else
        inv = ((const unsigned int*)mask)[nd] != 0u;

    float v = 0.f;
    if (!inv) {
        int zz = z[nd], yy = y[nd], xx = x[nd];
        v = fv[((b * CC + zz) * HF + yy) * WF + xx];
    }
    feat[idx] = v;
}

// ---------------------------------------------------------------------------
// Pack heads weights: g_W[k][c] = c<2 ? cls_w[k][c] : reg_w[k][c-2]
// ---------------------------------------------------------------------------
__global__ __launch_bounds__(256)
void pack_w_kernel(const float* __restrict__ cls_w,
                   const float* __restrict__ reg_w,
                   float* __restrict__ W)
{
    int idx = blockIdx.x * blockDim.x + threadIdx.x;
    if (idx >= 2 * DD * HN) return;
    int k = idx / HN, c = idx % HN;
    W[idx] = (c < 2) ? cls_w[k * 2 + c] : reg_w[k * 73 + (c - 2)];
}

// ---------------------------------------------------------------------------
// TF32 tensor-core GEMM with fragment-packed smem + 2-stage double buffering.
// C[z] = A[z] (MxK rm) @ B[z] (KxN rm). Block 128x128, Ktile 32, 8 warps,
// warp tile 32x64, mma.sync.m16n8k8.tf32.
// Shared layout (dynamic, 64KB):
//   A frags: sm[st*4096 + (ks*8+mb)*128 + lane*4 + r]    (st<2, ks<4, mb<8)
//   B frags: sm[8192 + st*4096 + (ks*16+nb)*64 + lane*2 + r]  (nb<16)
// MODE 0: plain A (stride lda). MODE 1: concat A=[A1|A2] rows of DD each.
// VECB: float4 B global loads (requires ldb%4==0 and full n-tiles).
// ---------------------------------------------------------------------------
__device__ __forceinline__ float f2tf32f(float f)
{
    unsigned int r;
    asm("cvt.rna.tf32.f32 %0, %1;" : "=r"(r) : "f"(f));
    return __uint_as_float(r);
}

template<int MODE, bool ADD_BIAS, bool VECB>
__global__ __launch_bounds__(256)
void gemm_tf32_db_kernel(const float* __restrict__ A,
                         const float* __restrict__ A2,
                         const float* __restrict__ B,
                         const float* __restrict__ bias,
                         float* __restrict__ C,
                         int M, int N, int K, int lda, int ldb,
                         size_t sA, size_t sB, size_t sC)
{
    extern __shared__ float sm[];

    const int tid  = threadIdx.x;
    const int lane = tid & 31;
    const int wid  = tid >> 5;
    const int gid  = lane >> 2;     // 0..7
    const int tg   = lane & 3;      // 0..3
    const int wm   = (wid & 3) * 32;
    const int wn   = (wid >> 2) * 64;
    const int mb0  = (wid & 3) * 2;
    const int nb0  = (wid >> 2) * 8;

    const int m0 = blockIdx.y * 128;
    const int n0 = blockIdx.x * 128;

    if (MODE == 0) A += (size_t)blockIdx.z * sA;
    B += (size_t)blockIdx.z * sB;
    C += (size_t)blockIdx.z * sC;

    float acc[2][8][4];
    #pragma unroll
    for (int i = 0; i < 2; i++)
        #pragma unroll
        for (int j = 0; j < 8; j++)
            #pragma unroll
            for (int q = 0; q < 4; q++) acc[i][j][q] = 0.f;

    float4 ra[4];
    float  rb[4][4];

    // ---- staging helpers ----
    auto loadA = [&](int kt) {
        #pragma unroll
        for (int i = 0; i < 4; i++) {
            int f4  = tid + i * 256;
            int m_l = f4 >> 3, kq = f4 & 7;
            int m = m0 + m_l, kg = kt + kq * 4;
            float4 v = make_float4(0.f, 0.f, 0.f, 0.f);
            if (m < M && kg < K) {
                const float* src;
                if (MODE == 1)
                    src = (kg < DD) ? &A[(size_t)m * DD + kg]
                                    : &A2[(size_t)m * DD + (kg - DD)];
                else
                    src = &A[(size_t)m * lda + kg];
                v = *(const float4*)src;
            }
            ra[i] = v;
        }
    };

    auto loadB = [&](int kt) {
        #pragma unroll
        for (int i = 0; i < 4; i++) {
            int f4  = tid + i * 256;
            int k_l = f4 >> 5, nq = f4 & 31;
            int kg = kt + k_l, n = n0 + nq * 4;
            if (VECB) {
                float4 v = make_float4(0.f, 0.f, 0.f, 0.f);
                if (kg < K && n + 3 < N)
                    v = *(const float4*)&B[(size_t)kg * ldb + n];
                rb[i][0] = v.x; rb[i][1] = v.y; rb[i][2] = v.z; rb[i][3] = v.w;
            } else {
                #pragma unroll
                for (int c = 0; c < 4; c++) {
                    int nn = n + c;
                    rb[i][c] = (kg < K && nn < N) ? B[(size_t)kg * ldb + nn] : 0.f;
                }
            }
        }
    };

    auto storeA = [&](int st) {
        float* base = sm + st * 4096;
        #pragma unroll
        for (int i = 0; i < 4; i++) {
            int f4  = tid + i * 256;
            int m_l = f4 >> 3, kq = f4 & 7;
            int ks = kq >> 1, half = kq & 1;
            int mb = m_l >> 4, mm = m_l & 15;
            int g = mm & 7, rh = mm >> 3;
            int r = rh + 2 * half;
            float* d = base + (ks * 8 + mb) * 128 + g * 16 + r;
            d[0]  = f2tf32f(ra[i].x);   // tg=0
            d[4]  = f2tf32f(ra[i].y);   // tg=1
            d[8]  = f2tf32f(ra[i].z);   // tg=2
            d[12] = f2tf32f(ra[i].w);   // tg=3
        }
    };

    auto storeB = [&](int st) {
        float* base = sm + 8192 + st * 4096;
        #pragma unroll
        for (int i = 0; i < 4; i++) {
            int f4  = tid + i * 256;
            int k_l = f4 >> 5, nq = f4 & 31;
            int ks = k_l >> 3, kk = k_l & 7;
            int t = kk & 3, r = kk >> 2;
            #pragma unroll
            for (int c = 0; c < 4; c++) {
                int n_l = nq * 4 + c;
                int nb = n_l >> 3, g = n_l & 7;
                base[(ks * 16 + nb) * 64 + (g * 4 + t) * 2 + r] = f2tf32f(rb[i][c]);
            }
        }
    };

    auto compute = [&](int st) {
        const float* Ab = sm + st * 4096;
        const float* Bb = sm + 8192 + st * 4096;
        #pragma unroll
        for (int ks = 0; ks < 4; ks++) {
            float4 av[2];
            av[0] = *(const float4*)(Ab + (ks * 8 + mb0)     * 128 + lane * 4);
            av[1] = *(const float4*)(Ab + (ks * 8 + mb0 + 1) * 128 + lane * 4);
            float2 bv[8];
            #pragma unroll
            for (int nt = 0; nt < 8; nt++)
                bv[nt] = *(const float2*)(Bb + (ks * 16 + nb0 + nt) * 64 + lane * 2);
            #pragma unroll
            for (int mt = 0; mt < 2; mt++) {
                unsigned int a0 = __float_as_uint(av[mt].x);
                unsigned int a1 = __float_as_uint(av[mt].y);
                unsigned int a2 = __float_as_uint(av[mt].z);
                unsigned int a3 = __float_as_uint(av[mt].w);
                #pragma unroll
                for (int nt = 0; nt < 8; nt++) {
                    asm volatile(
                        "mma.sync.aligned.m16n8k8.row.col.f32.tf32.tf32.f32 "
                        "{%0,%1,%2,%3}, {%4,%5,%6,%7}, {%8,%9}, {%0,%1,%2,%3};\n"
                        : "+f"(acc[mt][nt][0]), "+f"(acc[mt][nt][1]),
                          "+f"(acc[mt][nt][2]), "+f"(acc[mt][nt][3])
                        : "r"(a0), "r"(a1), "r"(a2), "r"(a3),
                          "r"(__float_as_uint(bv[nt].x)),
                          "r"(__float_as_uint(bv[nt].y)));
                }
            }
        }
    };

    // ---- prologue: fill stage 0 ----
    loadA(0); loadB(0);
    storeA(0); storeB(0);
    __syncthreads();

    int st = 0;
    for (int kt = 0; kt < K; kt += 32) {
        bool has_next = (kt + 32) < K;
        if (has_next) { loadA(kt + 32); loadB(kt + 32); }
        compute(st);
        if (has_next) {
            storeA(st ^ 1); storeB(st ^ 1);
            __syncthreads();
            st ^= 1;
        }
    }

    // ---- epilogue ----
    #pragma unroll
    for (int mt = 0; mt < 2; mt++) {
        #pragma unroll
        for (int nt = 0; nt < 8; nt++) {
            int row0 = m0 + wm + mt * 16 + gid;
            int col0 = n0 + wn + nt * 8 + tg * 2;
            #pragma unroll
            for (int q = 0; q < 4; q++) {
                int row = row0 + (q >> 1) * 8;
                int col = col0 + (q & 1);
                if (row < M && col < N) {
                    float v = acc[mt][nt][q];
                    if (ADD_BIAS) v += bias[col];
                    C[(size_t)row * N + col] = v;
                }
            }
        }
    }
}

// ---------------------------------------------------------------------------
// Row softmax over 999 logits + scatter into (N x N) with zero diagonal.
// ---------------------------------------------------------------------------
__global__ __launch_bounds__(256)
void softmax_scatter_kernel(const float* __restrict__ logits,
                            float* __restrict__ S)
{
    const int i = blockIdx.x;
    const int b = blockIdx.y;
    const float* __restrict__ row = logits + ((size_t)(b * NN + i)) * NM1;
    float* __restrict__ o = S + ((size_t)(b * NN + i)) * NN;

    __shared__ float sh[8];
    const int tid = threadIdx.x;
    const int lane = tid & 31, warp = tid >> 5;

    float rv[4];
    #pragma unroll
    for (int p = 0; p < 4; p++) {
        int k = tid + 256 * p;
        rv[p] = (k < NM1) ? row[k] : -1e30f;
    }

    float m = -1e30f;
    #pragma unroll
    for (int p = 0; p < 4; p++) m = fmaxf(m, rv[p]);
    #pragma unroll
    for (int off = 16; off; off >>= 1) m = fmaxf(m, __shfl_xor_sync(0xffffffffu, m, off));
    if (lane == 0) sh[warp] = m;
    __syncthreads();
    if (warp == 0) {
        float t = (lane < 8) ? sh[lane] : -1e30f;
        #pragma unroll
        for (int off = 16; off; off >>= 1) t = fmaxf(t, __shfl_xor_sync(0xffffffffu, t, off));
        if (lane == 0) sh[0] = t;
    }
    __syncthreads();
    m = sh[0];
    __syncthreads();

    float s = 0.f;
    float ev[4];
    #pragma unroll
    for (int p = 0; p < 4; p++) {
        int k = tid + 256 * p;
        float e = (k < NM1) ? __expf(rv[p] - m) : 0.f;
        ev[p] = e;
        s += e;
    }
    #pragma unroll
    for (int off = 16; off; off >>= 1) s += __shfl_xor_sync(0xffffffffu, s, off);
    if (lane == 0) sh[warp] = s;
    __syncthreads();
    if (warp == 0) {
        float t = (lane < 8) ? sh[lane] : 0.f;
        #pragma unroll
        for (int off = 16; off; off >>= 1) t += __shfl_xor_sync(0xffffffffu, t, off);
        if (lane == 0) sh[0] = t;
    }
    __syncthreads();
    const float inv = 1.f / sh[0];

    #pragma unroll
    for (int p = 0; p < 4; p++) {
        int k = tid + 256 * p;
        if (k < NM1) {
            int j = (k < i) ? k : k + 1;
            o[j] = ev[p] * inv;
        }
    }
    if (tid == 0) o[i] = 0.f;
}

// ---------------------------------------------------------------------------
// Heads epilogue: out[r][c] from ho (32000 x 75), biases, anchors.
// ---------------------------------------------------------------------------
__global__ __launch_bounds__(256)
void heads_epilogue_kernel(const float* __restrict__ ho,
                           const float* __restrict__ cls_b,
                           const float* __restrict__ reg_b,
                           const float* __restrict__ anchors,
                           float* __restrict__ out)
{
    int idx = blockIdx.x * blockDim.x + threadIdx.x;
    if (idx >= BB * NN * OUTC) return;
    int c = idx % OUTC;
    int r = idx / OUTC;
    int n = r % NN;
    float v;
    if (c < 2)       v = ho[(size_t)r * HN + c] + cls_b[c];
    else if (c < 4)  v = anchors[n * OUTC + c];
    else             v = ho[(size_t)r * HN + (c - 2)] + reg_b[c - 4]
                         + anchors[n * OUTC + c];
    out[idx] = v;
}

// ---------------------------------------------------------------------------
// Launch
// ---------------------------------------------------------------------------
#define GEMM_SMEM 65536

extern "C" void kernel_launch(void* const* d_in, const int* in_sizes, int n_in,
                              void* d_out, int out_size)
{
    const float* fv      = (const float*)d_in[0];
    const float* attn_w  = (const float*)d_in[1];
    const float* attn_b  = (const float*)d_in[2];
    const float* cls_w   = (const float*)d_in[3];
    const float* cls_b   = (const float*)d_in[4];
    const float* reg_w   = (const float*)d_in[5];
    const float* reg_b   = (const float*)d_in[6];
    const float* anchors = (const float*)d_in[7];
    const int*   z       = (const int*)d_in[8];
    const int*   y       = (const int*)d_in[9];
    const int*   x       = (const int*)d_in[10];
    const void*  mask    = d_in[11];
    float* out = (float*)d_out;

    float *feat, *logits, *S, *att, *ho, *W;
    cudaGetSymbolAddress((void**)&feat,   g_feat);
    cudaGetSymbolAddress((void**)&logits, g_logits);
    cudaGetSymbolAddress((void**)&S,      g_S);
    cudaGetSymbolAddress((void**)&att,    g_att);
    cudaGetSymbolAddress((void**)&ho,     g_ho);
    cudaGetSymbolAddress((void**)&W,      g_W);

    static int attr_done = 0;
    if (!attr_done) {
        cudaFuncSetAttribute(gemm_tf32_db_kernel<0, true,  false>,
                             cudaFuncAttributeMaxDynamicSharedMemorySize, GEMM_SMEM);
        cudaFuncSetAttribute(gemm_tf32_db_kernel<0, false, true>,
                             cudaFuncAttributeMaxDynamicSharedMemorySize, GEMM_SMEM);
        cudaFuncSetAttribute(gemm_tf32_db_kernel<1, false, false>,
                             cudaFuncAttributeMaxDynamicSharedMemorySize, GEMM_SMEM);
        attr_done = 1;
    }

    // 1) mask dtype detection
    detect_mask_kernel<<<1, 256>>>((const unsigned int*)mask, 190000);

    // 2) gather
    {
        int total = BB * NN * DD;
        gather_kernel<<<(total + 255) / 256, 256>>>(fv, z, y, x, mask, feat, total);
    }

    // 2b) pack heads weights
    pack_w_kernel<<<(2 * DD * HN + 255) / 256, 256>>>(cls_w, reg_w, W);

    // 3) logits = feat @ attn_w + attn_b   (per batch 1000x999, K=768; ldb=999 -> scalar B)
    {
        dim3 grid((NM1 + 127) / 128, (NN + 127) / 128, BB);
        gemm_tf32_db_kernel<0, true, false><<<grid, 256, GEMM_SMEM>>>(
            feat, nullptr, attn_w, attn_b, logits,
            NN, NM1, DD, DD, NM1,
            (size_t)NN * DD, 0, (size_t)NN * NM1);
    }

    // 4) softmax + scatter
    {
        dim3 grid(NN, BB);
        softmax_scatter_kernel<<<grid, 256>>>(logits, S);
    }

    // 5) att = S @ feat                    (per batch 1000x768, K=1000; ldb=768 -> vec B)
    {
        dim3 grid((DD + 127) / 128, (NN + 127) / 128, BB);
        gemm_tf32_db_kernel<0, false, true><<<grid, 256, GEMM_SMEM>>>(
            S, nullptr, feat, nullptr, att,
            NN, DD, NN, NN, DD,
            (size_t)NN * NN, (size_t)NN * DD, (size_t)NN * DD);
    }

    // 6) heads GEMM: [att|feat] (32000 x 1536) @ W (1536 x 75; ldb=75 -> scalar B)
    {
        dim3 grid(1, (BB * NN + 127) / 128, 1);
        gemm_tf32_db_kernel<1, false, false><<<grid, 256, GEMM_SMEM>>>(
            att, feat, W, nullptr, ho,
            BB * NN, HN, 2 * DD, 0, HN,
            0, 0, 0);
    }

    // 7) heads epilogue
    {
        int total = BB * NN * OUTC;
        heads_epilogue_kernel<<<(total + 255) / 256, 256>>>(ho, cls_b, reg_b,
                                                            anchors, out);
    }
}